// round 5
// baseline (speedup 1.0000x reference)
#include <cuda_runtime.h>
#include <cuda_bf16.h>
#include <cstdint>

// Problem constants (graph structure fully known: B fully-connected 64-node
// graphs with self loops, source-major edges).
#define NB     512
#define NN     64
#define INCH   256
#define KTOP   20
#define NTOT   (NB * NN)          // 32768 nodes
#define NEDGE_OUT (NTOT * KTOP)   // 655360

// Scratch
__device__ float g_y[(size_t)NTOT * 128];   // y[node][0:64]=x_l, [64:128]=x_r
// W fragments in mma.m16n8k16 B-fragment order: [kc][s][nt][lane] -> uint2
__device__ uint2 g_wf[16 * 3 * 16 * 32];
__constant__ float c_att[64];

// ---------------- packed f32x2 helpers (attn kernel) ----------------
static __device__ __forceinline__ double pk2(float x, float y) {
    double r; asm("mov.b64 %0, {%1, %2};" : "=d"(r) : "f"(x), "f"(y)); return r;
}
static __device__ __forceinline__ void upk2(double v, float& x, float& y) {
    asm("mov.b64 {%0, %1}, %2;" : "=f"(x), "=f"(y) : "d"(v));
}
static __device__ __forceinline__ double fma2(double a, double b, double c) {
    double r; asm("fma.rn.f32x2 %0, %1, %2, %3;" : "=d"(r) : "d"(a), "d"(b), "d"(c)); return r;
}
static __device__ __forceinline__ double add2(double a, double b) {
    double r; asm("add.rn.f32x2 %0, %1, %2;" : "=d"(r) : "d"(a), "d"(b)); return r;
}
static __device__ __forceinline__ double and2(double a, double m) {
    double r; asm("and.b64 %0, %1, %2;" : "=d"(r) : "d"(a), "d"(m)); return r;
}

// ---------------- mma / ldmatrix helpers (baseline PTX, sm_80 features) -----
static __device__ __forceinline__ uint32_t smem_u32(const void* p) {
    uint32_t a;
    asm("{ .reg .u64 t; cvta.to.shared.u64 t, %1; cvt.u32.u64 %0, t; }"
        : "=r"(a) : "l"(p));
    return a;
}
static __device__ __forceinline__ void ldmat4(uint32_t* r, uint32_t addr) {
    asm volatile("ldmatrix.sync.aligned.m8n8.x4.shared.b16 {%0,%1,%2,%3}, [%4];"
                 : "=r"(r[0]), "=r"(r[1]), "=r"(r[2]), "=r"(r[3]) : "r"(addr));
}
static __device__ __forceinline__ void mma16816(float* c, const uint32_t* a,
                                                uint32_t b0, uint32_t b1) {
    asm volatile(
        "mma.sync.aligned.m16n8k16.row.col.f32.bf16.bf16.f32 "
        "{%0,%1,%2,%3}, {%4,%5,%6,%7}, {%8,%9}, {%0,%1,%2,%3};"
        : "+f"(c[0]), "+f"(c[1]), "+f"(c[2]), "+f"(c[3])
        : "r"(a[0]), "r"(a[1]), "r"(a[2]), "r"(a[3]), "r"(b0), "r"(b1));
}

// bf16x3 split
static __device__ __forceinline__ void split3(
    float a, unsigned short& s0, unsigned short& s1, unsigned short& s2)
{
    __nv_bfloat16 h0 = __float2bfloat16(a);
    float r1 = a - __bfloat162float(h0);
    __nv_bfloat16 h1 = __float2bfloat16(r1);
    float r2 = r1 - __bfloat162float(h1);
    __nv_bfloat16 h2 = __float2bfloat16(r2);
    s0 = __bfloat16_as_ushort(h0);
    s1 = __bfloat16_as_ushort(h1);
    s2 = __bfloat16_as_ushort(h2);
}

// ---------------------------------------------------------------------------
// Kernel 0: W = [Wl;Wr] -> bf16x3 B-fragments for mma.m16n8k16.
// One thread per (kc, nt, lane): 4 loads, 4 split3, 3 uint2 stores.
// ---------------------------------------------------------------------------
__global__ __launch_bounds__(256) void splitwf_kernel(
    const float* __restrict__ Wl, const float* __restrict__ Wr)
{
    int g = blockIdx.x * 256 + threadIdx.x;     // < 8192
    int lane = g & 31, nt = (g >> 5) & 15, kc = g >> 9;
    int n = nt * 8 + (lane >> 2);
    int k = kc * 16 + 2 * (lane & 3);
    const float* wrow = (n < 64) ? (Wl + (size_t)n * INCH)
                                 : (Wr + (size_t)(n - 64) * INCH);
    float2 wlo = *(const float2*)(wrow + k);
    float2 whi = *(const float2*)(wrow + k + 8);
    unsigned short a0[4], a1[4], a2[4];
    split3(wlo.x, a0[0], a1[0], a2[0]);
    split3(wlo.y, a0[1], a1[1], a2[1]);
    split3(whi.x, a0[2], a1[2], a2[2]);
    split3(whi.y, a0[3], a1[3], a2[3]);
    size_t base = ((size_t)(kc * 3) * 16 + nt) * 32 + lane;
    g_wf[base]            = make_uint2((uint32_t)a0[0] | ((uint32_t)a0[1] << 16),
                                       (uint32_t)a0[2] | ((uint32_t)a0[3] << 16));
    g_wf[base + 512]      = make_uint2((uint32_t)a1[0] | ((uint32_t)a1[1] << 16),
                                       (uint32_t)a1[2] | ((uint32_t)a1[3] << 16));
    g_wf[base + 1024]     = make_uint2((uint32_t)a2[0] | ((uint32_t)a2[1] << 16),
                                       (uint32_t)a2[2] | ((uint32_t)a2[3] << 16));
}

// ---------------------------------------------------------------------------
// Kernel 1: HMMA dual GEMM  y = x @ [Wl;Wr]^T + bias  (bf16x3, 6 products)
// 256 blocks x 256 threads; 128x128 per block; double-buffered A staging.
// ---------------------------------------------------------------------------
__global__ __launch_bounds__(256) void gemm_hmma(
    const float* __restrict__ x,
    const float* __restrict__ bl, const float* __restrict__ br)
{
    __shared__ __align__(16) unsigned short sA[2][3][128 * 24];  // 36.9KB
    __shared__ float sbias[128];

    const int t = threadIdx.x, wid = t >> 5, lane = t & 31;
    const int m0 = blockIdx.x * 128;
    if (t < 128) sbias[t] = (t < 64) ? bl[t] : br[t - 64];

    float acc[16][4];
#pragma unroll
    for (int nt = 0; nt < 16; nt++)
#pragma unroll
        for (int v = 0; v < 4; v++) acc[nt][v] = 0.f;

    // staging lambda: chunk kc -> buffer buf
    auto stage = [&](int kc, int buf) {
#pragma unroll
        for (int ss = 0; ss < 2; ss++) {
            int v = t + ss * 256;          // 0..511 float4 ids
            int row = v >> 2, q = v & 3;
            float4 p = *(const float4*)(x + (size_t)(m0 + row) * INCH + kc * 16 + q * 4);
            unsigned short a0[4], a1[4], a2[4];
            split3(p.x, a0[0], a1[0], a2[0]);
            split3(p.y, a0[1], a1[1], a2[1]);
            split3(p.z, a0[2], a1[2], a2[2]);
            split3(p.w, a0[3], a1[3], a2[3]);
            int off = row * 24 + q * 4;
            *(uint2*)&sA[buf][0][off] = make_uint2((uint32_t)a0[0] | ((uint32_t)a0[1] << 16),
                                                   (uint32_t)a0[2] | ((uint32_t)a0[3] << 16));
            *(uint2*)&sA[buf][1][off] = make_uint2((uint32_t)a1[0] | ((uint32_t)a1[1] << 16),
                                                   (uint32_t)a1[2] | ((uint32_t)a1[3] << 16));
            *(uint2*)&sA[buf][2][off] = make_uint2((uint32_t)a2[0] | ((uint32_t)a2[1] << 16),
                                                   (uint32_t)a2[2] | ((uint32_t)a2[3] << 16));
        }
    };

    // ldmatrix lane offset within a buffer/split
    const uint32_t aoff = (uint32_t)((wid * 16 + ((lane >> 3) & 1) * 8 + (lane & 7)) * 24
                                     + (lane >> 4) * 8) * 2;

    stage(0, 0);
    __syncthreads();

    int p = 0;
    for (int kc = 0; kc < 16; kc++) {
        uint32_t A0[4], A1[4], A2[4];
        uint32_t b0 = smem_u32(&sA[p][0][0]);
        ldmat4(A0, b0 + aoff);
        ldmat4(A1, b0 + 128 * 24 * 2 + aoff);
        ldmat4(A2, b0 + 2 * 128 * 24 * 2 + aoff);

        if (kc < 15) stage(kc + 1, p ^ 1);   // overlaps with MMA issue below

        const uint2* wf = g_wf + (size_t)(kc * 3) * 512 + lane;
#pragma unroll
        for (int nt = 0; nt < 16; nt++) {
            uint2 B0 = __ldg(wf + nt * 32);
            uint2 B1 = __ldg(wf + 512 + nt * 32);
            uint2 B2 = __ldg(wf + 1024 + nt * 32);
            mma16816(acc[nt], A0, B0.x, B0.y);   // a0*b0
            mma16816(acc[nt], A0, B1.x, B1.y);   // a0*b1
            mma16816(acc[nt], A1, B0.x, B0.y);   // a1*b0
            mma16816(acc[nt], A1, B1.x, B1.y);   // a1*b1
            mma16816(acc[nt], A0, B2.x, B2.y);   // a0*b2
            mma16816(acc[nt], A2, B0.x, B0.y);   // a2*b0
        }
        __syncthreads();
        p ^= 1;
    }

    // epilogue: C frag (c0,c1)@(r, 2c),(r,2c+1); (c2,c3)@(r+8, ...)
    const int r0 = m0 + wid * 16 + (lane >> 2);
    const int cbase = 2 * (lane & 3);
#pragma unroll
    for (int nt = 0; nt < 16; nt++) {
        int c = nt * 8 + cbase;
        float2 o0 = make_float2(acc[nt][0] + sbias[c], acc[nt][1] + sbias[c + 1]);
        float2 o1 = make_float2(acc[nt][2] + sbias[c], acc[nt][3] + sbias[c + 1]);
        *(float2*)&g_y[(size_t)r0 * 128 + c] = o0;
        *(float2*)&g_y[(size_t)(r0 + 8) * 128 + c] = o1;
    }
}

// ---------------------------------------------------------------------------
// Kernel 2: per-graph attention. sa aliased onto sxl (32.3KB smem),
// __launch_bounds__(256,4) -> 4 CTAs/SM. Math order identical to R4.
// ---------------------------------------------------------------------------
__global__ __launch_bounds__(256, 4) void attn_kernel(
    const float* __restrict__ att, float* __restrict__ out)
{
    __shared__ float sU [4096];   // xl (pair-interleaved, swizzled), later alpha
    __shared__ float sxr[4096];   // [j*64 + (d ^ ((j>>2)&15))]
    __shared__ float sR [64];

    const int t = threadIdx.x;
    const int b = blockIdx.x;
    const float* yg = g_y + (size_t)b * NN * 128;

    // Phase 1: stage x_l -> sU, x_r -> sxr
#pragma unroll
    for (int s = 0; s < 8; s++) {
        int v = t + s * 256;
        int node = v >> 5, q = v & 31;
        float4 p = *(const float4*)(yg + (size_t)node * 128 + q * 4);
        if (q < 16) {
            int pi = node >> 1, comp = node & 1, swz = pi & 3;
            int d0 = q * 4;
            int base = pi * 128 + comp;
            sU[base + ((d0 + 0) ^ swz) * 2] = p.x;
            sU[base + ((d0 + 1) ^ swz) * 2] = p.y;
            sU[base + ((d0 + 2) ^ swz) * 2] = p.z;
            sU[base + ((d0 + 3) ^ swz) * 2] = p.w;
        } else {
            int d0 = (q - 16) * 4, sw = (node >> 2) & 15;
            int base = node * 64;
            sxr[base + ((d0 + 0) ^ sw)] = p.x;
            sxr[base + ((d0 + 1) ^ sw)] = p.y;
            sxr[base + ((d0 + 2) ^ sw)] = p.z;
            sxr[base + ((d0 + 3) ^ sw)] = p.w;
        }
    }
    __syncthreads();

    // Phase 1.5: R[j] = 0.6 * sum_d att[d]*xr[j][d]  ->  sR[j]
    {
        int w = t >> 5, lane = t & 31;
        float a0 = 0.6f * att[lane];
        float a1 = 0.6f * att[lane + 32];
#pragma unroll
        for (int jj = 0; jj < 8; jj++) {
            int j = w * 8 + jj, sw = (j >> 2) & 15;
            float r = fmaf(a0, sxr[j * 64 + (lane ^ sw)],
                           a1 * sxr[j * 64 + ((lane + 32) ^ sw)]);
#pragma unroll
            for (int off = 16; off; off >>= 1)
                r += __shfl_xor_sync(0xffffffffu, r, off);
            if (lane == 0) sR[j] = r;
        }
    }
    __syncthreads();

    const int tR = t >> 4, tC = t & 15;
    float Rj[4];
#pragma unroll
    for (int jj = 0; jj < 4; jj++) Rj[jj] = sR[tC * 4 + jj];

    // Phase 2: A[i][j] = sum_d (0.4 att_d)|xl+xr|, packed over i-pairs
    {
        const double ABSM = __longlong_as_double(0x7fffffff7fffffffLL);
        const double* sxl2 = (const double*)sU;
        const double* pA = sxl2 + (2 * tR) * 64;
        const double* pB = sxl2 + (2 * tR + 1) * 64;
        const float*  pR = sxr + (4 * tC) * 64;
        const int swz0 = (2 * tR) & 3;
        double acc[2][4];
#pragma unroll
        for (int pr = 0; pr < 2; pr++)
#pragma unroll
            for (int jj = 0; jj < 4; jj++) acc[pr][jj] = 0.0;

#pragma unroll 8
        for (int d = 0; d < 64; d++) {
            int dd = d ^ swz0;
            double xa = pA[dd];
            double xb = pB[dd ^ 1];
            int ddr = d ^ tC;
            double r0 = pk2(pR[ddr],        pR[ddr]);
            double r1 = pk2(pR[64 + ddr],   pR[64 + ddr]);
            double r2 = pk2(pR[128 + ddr],  pR[128 + ddr]);
            double r3 = pk2(pR[192 + ddr],  pR[192 + ddr]);
            float a4 = 0.4f * c_att[d];
            double a42 = pk2(a4, a4);
            acc[0][0] = fma2(a42, and2(add2(xa, r0), ABSM), acc[0][0]);
            acc[0][1] = fma2(a42, and2(add2(xa, r1), ABSM), acc[0][1]);
            acc[0][2] = fma2(a42, and2(add2(xa, r2), ABSM), acc[0][2]);
            acc[0][3] = fma2(a42, and2(add2(xa, r3), ABSM), acc[0][3]);
            acc[1][0] = fma2(a42, and2(add2(xb, r0), ABSM), acc[1][0]);
            acc[1][1] = fma2(a42, and2(add2(xb, r1), ABSM), acc[1][1]);
            acc[1][2] = fma2(a42, and2(add2(xb, r2), ABSM), acc[1][2]);
            acc[1][3] = fma2(a42, and2(add2(xb, r3), ABSM), acc[1][3]);
        }

        __syncthreads();   // all xl reads done -> safe to overwrite sU with alpha
#pragma unroll
        for (int pr = 0; pr < 2; pr++)
#pragma unroll
            for (int jj = 0; jj < 4; jj++) {
                float lo, hi; upk2(acc[pr][jj], lo, hi);
                int i0 = tR * 4 + pr * 2, j = tC * 4 + jj;
                sU[i0 * 64 + j]       = lo + Rj[jj];
                sU[(i0 + 1) * 64 + j] = hi + Rj[jj];
            }
    }
    __syncthreads();

    // ---- Phase 3: softmax + packed-key bitonic top-20 ----
    const int w = t >> 5, lane = t & 31;
#pragma unroll 1
    for (int rr = 0; rr < 8; rr++) {
        int i = w * 8 + rr;
        float v0 = sU[i * 64 + lane];
        float v1 = sU[i * 64 + 32 + lane];

        float m = fmaxf(v0, v1);
#pragma unroll
        for (int off = 16; off; off >>= 1)
            m = fmaxf(m, __shfl_xor_sync(0xffffffffu, m, off));
        float e0 = expf(v0 - m), e1 = expf(v1 - m);
        float ssum = e0 + e1;
#pragma unroll
        for (int off = 16; off; off >>= 1)
            ssum += __shfl_xor_sync(0xffffffffu, ssum, off);
        float inv = 1.0f / ssum;
        v0 = e0 * inv;
        v1 = e1 * inv;
        if (i < 32) { if (lane == i)      v0 = 0.f; }
        else        { if (lane == i - 32) v1 = 0.f; }

        // store exact values for post-sort gather
        sU[i * 64 + lane]      = v0;
        sU[i * 64 + 32 + lane] = v1;
        __syncwarp();

        // keys: value bits (positive -> monotone) with low 6 bits = 63-index
        uint32_t k0 = (__float_as_uint(v0) & 0xFFFFFFC0u) | (uint32_t)(63 - lane);
        uint32_t k1 = (__float_as_uint(v1) & 0xFFFFFFC0u) | (uint32_t)(31 - lane);

        // bitonic sort 64 keys descending; element pos: e0=lane, e1=lane+32
#pragma unroll
        for (int kk = 2; kk <= 32; kk <<= 1) {
#pragma unroll
            for (int j = kk >> 1; j >= 1; j >>= 1) {
                uint32_t o0 = __shfl_xor_sync(0xffffffffu, k0, j);
                uint32_t o1 = __shfl_xor_sync(0xffffffffu, k1, j);
                bool up = ((lane & j) == 0);
                bool d0c = ((lane & kk) == 0);
                bool d1c = (((lane + 32) & kk) == 0);
                k0 = (up == d0c) ? max(k0, o0) : min(k0, o0);
                k1 = (up == d1c) ? max(k1, o1) : min(k1, o1);
            }
        }
        { // kk=64, j=32: cross-register, descending for all
            uint32_t mx = max(k0, k1), mn = min(k0, k1);
            k0 = mx; k1 = mn;
        }
#pragma unroll
        for (int j = 16; j >= 1; j >>= 1) {   // kk=64 tail, descending
            uint32_t o0 = __shfl_xor_sync(0xffffffffu, k0, j);
            uint32_t o1 = __shfl_xor_sync(0xffffffffu, k1, j);
            bool up = ((lane & j) == 0);
            k0 = up ? max(k0, o0) : min(k0, o0);
            k1 = up ? max(k1, o1) : min(k1, o1);
        }
        __syncwarp();

        if (lane < KTOP) {
            int j = 63 - (int)(k0 & 63u);
            float av = sU[i * 64 + j];
            int gi = b * NN + i;
            size_t e = (size_t)gi * KTOP + lane;
            out[e]                 = (float)gi;
            out[NEDGE_OUT + e]     = (float)(b * NN + j);
            out[2 * NEDGE_OUT + e] = av;
        }
        __syncwarp();
    }
}

// ---------------------------------------------------------------------------
extern "C" void kernel_launch(void* const* d_in, const int* in_sizes, int n_in,
                              void* d_out, int out_size)
{
    const float* x   = (const float*)d_in[0];
    const float* Wl  = (const float*)d_in[3];
    const float* bl  = (const float*)d_in[4];
    const float* Wr  = (const float*)d_in[5];
    const float* br  = (const float*)d_in[6];
    const float* att = (const float*)d_in[7];

    cudaMemcpyToSymbolAsync(c_att, att, 64 * sizeof(float), 0,
                            cudaMemcpyDeviceToDevice);
    splitwf_kernel<<<32, 256>>>(Wl, Wr);
    gemm_hmma<<<NTOT / 128, 256>>>(x, bl, br);
    attn_kernel<<<NB, 256>>>(att, (float*)d_out);
}

// round 6
// speedup vs baseline: 1.0108x; 1.0108x over previous
#include <cuda_runtime.h>
#include <cuda_bf16.h>
#include <cstdint>

#define NB     512
#define NN     64
#define INCH   256
#define KTOP   20
#define NTOT   (NB * NN)          // 32768 nodes
#define NEDGE_OUT (NTOT * KTOP)   // 655360

__device__ float g_y[(size_t)NTOT * 128];   // y[node][0:64]=x_l, [64:128]=x_r
__device__ uint2 g_wf[16 * 3 * 16 * 32];    // W frags [kc][s][nt][lane]
__constant__ float c_att[64];

// ---------------- packed f32x2 helpers ----------------
static __device__ __forceinline__ double pk2(float x, float y) {
    double r; asm("mov.b64 %0, {%1, %2};" : "=d"(r) : "f"(x), "f"(y)); return r;
}
static __device__ __forceinline__ void upk2(double v, float& x, float& y) {
    asm("mov.b64 {%0, %1}, %2;" : "=f"(x), "=f"(y) : "d"(v));
}
static __device__ __forceinline__ double fma2(double a, double b, double c) {
    double r; asm("fma.rn.f32x2 %0, %1, %2, %3;" : "=d"(r) : "d"(a), "d"(b), "d"(c)); return r;
}
static __device__ __forceinline__ double add2(double a, double b) {
    double r; asm("add.rn.f32x2 %0, %1, %2;" : "=d"(r) : "d"(a), "d"(b)); return r;
}
static __device__ __forceinline__ double and2(double a, double m) {
    double r; asm("and.b64 %0, %1, %2;" : "=d"(r) : "d"(a), "d"(m)); return r;
}

// ---------------- mma / ldmatrix helpers ----------------
static __device__ __forceinline__ uint32_t smem_u32(const void* p) {
    uint32_t a;
    asm("{ .reg .u64 t; cvta.to.shared.u64 t, %1; cvt.u32.u64 %0, t; }"
        : "=r"(a) : "l"(p));
    return a;
}
static __device__ __forceinline__ void ldmat4(uint32_t* r, uint32_t addr) {
    asm volatile("ldmatrix.sync.aligned.m8n8.x4.shared.b16 {%0,%1,%2,%3}, [%4];"
                 : "=r"(r[0]), "=r"(r[1]), "=r"(r[2]), "=r"(r[3]) : "r"(addr));
}
static __device__ __forceinline__ void mma16816(float* c, const uint32_t* a,
                                                uint32_t b0, uint32_t b1) {
    asm volatile(
        "mma.sync.aligned.m16n8k16.row.col.f32.bf16.bf16.f32 "
        "{%0,%1,%2,%3}, {%4,%5,%6,%7}, {%8,%9}, {%0,%1,%2,%3};"
        : "+f"(c[0]), "+f"(c[1]), "+f"(c[2]), "+f"(c[3])
        : "r"(a[0]), "r"(a[1]), "r"(a[2]), "r"(a[3]), "r"(b0), "r"(b1));
}

static __device__ __forceinline__ void split3(
    float a, unsigned short& s0, unsigned short& s1, unsigned short& s2)
{
    __nv_bfloat16 h0 = __float2bfloat16(a);
    float r1 = a - __bfloat162float(h0);
    __nv_bfloat16 h1 = __float2bfloat16(r1);
    float r2 = r1 - __bfloat162float(h1);
    __nv_bfloat16 h2 = __float2bfloat16(r2);
    s0 = __bfloat16_as_ushort(h0);
    s1 = __bfloat16_as_ushort(h1);
    s2 = __bfloat16_as_ushort(h2);
}

// ---------------------------------------------------------------------------
// Kernel 0: W -> bf16x3 B-fragments (lean version, measured neutral)
// ---------------------------------------------------------------------------
__global__ __launch_bounds__(256) void splitwf_kernel(
    const float* __restrict__ Wl, const float* __restrict__ Wr)
{
    int g = blockIdx.x * 256 + threadIdx.x;     // < 8192
    int lane = g & 31, nt = (g >> 5) & 15, kc = g >> 9;
    int n = nt * 8 + (lane >> 2);
    int k = kc * 16 + 2 * (lane & 3);
    const float* wrow = (n < 64) ? (Wl + (size_t)n * INCH)
                                 : (Wr + (size_t)(n - 64) * INCH);
    float2 wlo = *(const float2*)(wrow + k);
    float2 whi = *(const float2*)(wrow + k + 8);
    unsigned short a0[4], a1[4], a2[4];
    split3(wlo.x, a0[0], a1[0], a2[0]);
    split3(wlo.y, a0[1], a1[1], a2[1]);
    split3(whi.x, a0[2], a1[2], a2[2]);
    split3(whi.y, a0[3], a1[3], a2[3]);
    size_t base = ((size_t)(kc * 3) * 16 + nt) * 32 + lane;
    g_wf[base]        = make_uint2((uint32_t)a0[0] | ((uint32_t)a0[1] << 16),
                                   (uint32_t)a0[2] | ((uint32_t)a0[3] << 16));
    g_wf[base + 512]  = make_uint2((uint32_t)a1[0] | ((uint32_t)a1[1] << 16),
                                   (uint32_t)a1[2] | ((uint32_t)a1[3] << 16));
    g_wf[base + 1024] = make_uint2((uint32_t)a2[0] | ((uint32_t)a2[1] << 16),
                                   (uint32_t)a2[2] | ((uint32_t)a2[3] << 16));
}

// ---------------------------------------------------------------------------
// Kernel 1: HMMA dual GEMM, double-buffered A staging (the R5 change on trial)
// ---------------------------------------------------------------------------
__global__ __launch_bounds__(256) void gemm_hmma(
    const float* __restrict__ x,
    const float* __restrict__ bl, const float* __restrict__ br)
{
    __shared__ __align__(16) unsigned short sA[2][3][128 * 24];  // 36.9KB
    __shared__ float sbias[128];

    const int t = threadIdx.x, wid = t >> 5, lane = t & 31;
    const int m0 = blockIdx.x * 128;
    if (t < 128) sbias[t] = (t < 64) ? bl[t] : br[t - 64];

    float acc[16][4];
#pragma unroll
    for (int nt = 0; nt < 16; nt++)
#pragma unroll
        for (int v = 0; v < 4; v++) acc[nt][v] = 0.f;

    auto stage = [&](int kc, int buf) {
#pragma unroll
        for (int ss = 0; ss < 2; ss++) {
            int v = t + ss * 256;
            int row = v >> 2, q = v & 3;
            float4 p = *(const float4*)(x + (size_t)(m0 + row) * INCH + kc * 16 + q * 4);
            unsigned short a0[4], a1[4], a2[4];
            split3(p.x, a0[0], a1[0], a2[0]);
            split3(p.y, a0[1], a1[1], a2[1]);
            split3(p.z, a0[2], a1[2], a2[2]);
            split3(p.w, a0[3], a1[3], a2[3]);
            int off = row * 24 + q * 4;
            *(uint2*)&sA[buf][0][off] = make_uint2((uint32_t)a0[0] | ((uint32_t)a0[1] << 16),
                                                   (uint32_t)a0[2] | ((uint32_t)a0[3] << 16));
            *(uint2*)&sA[buf][1][off] = make_uint2((uint32_t)a1[0] | ((uint32_t)a1[1] << 16),
                                                   (uint32_t)a1[2] | ((uint32_t)a1[3] << 16));
            *(uint2*)&sA[buf][2][off] = make_uint2((uint32_t)a2[0] | ((uint32_t)a2[1] << 16),
                                                   (uint32_t)a2[2] | ((uint32_t)a2[3] << 16));
        }
    };

    const uint32_t aoff = (uint32_t)((wid * 16 + ((lane >> 3) & 1) * 8 + (lane & 7)) * 24
                                     + (lane >> 4) * 8) * 2;

    stage(0, 0);
    __syncthreads();

    int p = 0;
    for (int kc = 0; kc < 16; kc++) {
        uint32_t A0[4], A1[4], A2[4];
        uint32_t b0 = smem_u32(&sA[p][0][0]);
        ldmat4(A0, b0 + aoff);
        ldmat4(A1, b0 + 128 * 24 * 2 + aoff);
        ldmat4(A2, b0 + 2 * 128 * 24 * 2 + aoff);

        if (kc < 15) stage(kc + 1, p ^ 1);

        const uint2* wf = g_wf + (size_t)(kc * 3) * 512 + lane;
#pragma unroll
        for (int nt = 0; nt < 16; nt++) {
            uint2 B0 = __ldg(wf + nt * 32);
            uint2 B1 = __ldg(wf + 512 + nt * 32);
            uint2 B2 = __ldg(wf + 1024 + nt * 32);
            mma16816(acc[nt], A0, B0.x, B0.y);
            mma16816(acc[nt], A0, B1.x, B1.y);
            mma16816(acc[nt], A1, B0.x, B0.y);
            mma16816(acc[nt], A1, B1.x, B1.y);
            mma16816(acc[nt], A0, B2.x, B2.y);
            mma16816(acc[nt], A2, B0.x, B0.y);
        }
        __syncthreads();
        p ^= 1;
    }

    const int r0 = m0 + wid * 16 + (lane >> 2);
    const int cbase = 2 * (lane & 3);
#pragma unroll
    for (int nt = 0; nt < 16; nt++) {
        int c = nt * 8 + cbase;
        float2 o0 = make_float2(acc[nt][0] + sbias[c], acc[nt][1] + sbias[c + 1]);
        float2 o1 = make_float2(acc[nt][2] + sbias[c], acc[nt][3] + sbias[c + 1]);
        *(float2*)&g_y[(size_t)r0 * 128 + c] = o0;
        *(float2*)&g_y[(size_t)(r0 + 8) * 128 + c] = o1;
    }
}

// ---------------------------------------------------------------------------
// Kernel 2: attention — EXACT R4 version (no reg cap, separate sa, 48KB smem)
// ---------------------------------------------------------------------------
__global__ __launch_bounds__(256) void attn_kernel(
    const float* __restrict__ att, float* __restrict__ out)
{
    __shared__ float sxl[4096];
    __shared__ float sxr[4096];
    __shared__ float sa [4096];

    const int t = threadIdx.x;
    const int b = blockIdx.x;
    const float* yg = g_y + (size_t)b * NN * 128;

#pragma unroll
    for (int s = 0; s < 8; s++) {
        int v = t + s * 256;
        int node = v >> 5, q = v & 31;
        float4 p = *(const float4*)(yg + (size_t)node * 128 + q * 4);
        if (q < 16) {
            int pi = node >> 1, comp = node & 1, swz = pi & 3;
            int d0 = q * 4;
            int base = pi * 128 + comp;
            sxl[base + ((d0 + 0) ^ swz) * 2] = p.x;
            sxl[base + ((d0 + 1) ^ swz) * 2] = p.y;
            sxl[base + ((d0 + 2) ^ swz) * 2] = p.z;
            sxl[base + ((d0 + 3) ^ swz) * 2] = p.w;
        } else {
            int d0 = (q - 16) * 4, sw = (node >> 2) & 15;
            int base = node * 64;
            sxr[base + ((d0 + 0) ^ sw)] = p.x;
            sxr[base + ((d0 + 1) ^ sw)] = p.y;
            sxr[base + ((d0 + 2) ^ sw)] = p.z;
            sxr[base + ((d0 + 3) ^ sw)] = p.w;
        }
    }
    __syncthreads();

    {
        int w = t >> 5, lane = t & 31;
        float a0 = 0.6f * att[lane];
        float a1 = 0.6f * att[lane + 32];
#pragma unroll
        for (int jj = 0; jj < 8; jj++) {
            int j = w * 8 + jj, sw = (j >> 2) & 15;
            float r = fmaf(a0, sxr[j * 64 + (lane ^ sw)],
                           a1 * sxr[j * 64 + ((lane + 32) ^ sw)]);
#pragma unroll
            for (int off = 16; off; off >>= 1)
                r += __shfl_xor_sync(0xffffffffu, r, off);
            if (lane == 0) sa[j] = r;
        }
    }
    __syncthreads();

    const int tR = t >> 4, tC = t & 15;
    float Rj[4];
#pragma unroll
    for (int jj = 0; jj < 4; jj++) Rj[jj] = sa[tC * 4 + jj];

    {
        const double ABSM = __longlong_as_double(0x7fffffff7fffffffLL);
        const double* sxl2 = (const double*)sxl;
        const double* pA = sxl2 + (2 * tR) * 64;
        const double* pB = sxl2 + (2 * tR + 1) * 64;
        const float*  pR = sxr + (4 * tC) * 64;
        const int swz0 = (2 * tR) & 3;
        double acc[2][4];
#pragma unroll
        for (int pr = 0; pr < 2; pr++)
#pragma unroll
            for (int jj = 0; jj < 4; jj++) acc[pr][jj] = 0.0;

#pragma unroll 8
        for (int d = 0; d < 64; d++) {
            int dd = d ^ swz0;
            double xa = pA[dd];
            double xb = pB[dd ^ 1];
            int ddr = d ^ tC;
            double r0 = pk2(pR[ddr],        pR[ddr]);
            double r1 = pk2(pR[64 + ddr],   pR[64 + ddr]);
            double r2 = pk2(pR[128 + ddr],  pR[128 + ddr]);
            double r3 = pk2(pR[192 + ddr],  pR[192 + ddr]);
            float a4 = 0.4f * c_att[d];
            double a42 = pk2(a4, a4);
            acc[0][0] = fma2(a42, and2(add2(xa, r0), ABSM), acc[0][0]);
            acc[0][1] = fma2(a42, and2(add2(xa, r1), ABSM), acc[0][1]);
            acc[0][2] = fma2(a42, and2(add2(xa, r2), ABSM), acc[0][2]);
            acc[0][3] = fma2(a42, and2(add2(xa, r3), ABSM), acc[0][3]);
            acc[1][0] = fma2(a42, and2(add2(xb, r0), ABSM), acc[1][0]);
            acc[1][1] = fma2(a42, and2(add2(xb, r1), ABSM), acc[1][1]);
            acc[1][2] = fma2(a42, and2(add2(xb, r2), ABSM), acc[1][2]);
            acc[1][3] = fma2(a42, and2(add2(xb, r3), ABSM), acc[1][3]);
        }

        __syncthreads();
#pragma unroll
        for (int pr = 0; pr < 2; pr++)
#pragma unroll
            for (int jj = 0; jj < 4; jj++) {
                float lo, hi; upk2(acc[pr][jj], lo, hi);
                int i0 = tR * 4 + pr * 2, j = tC * 4 + jj;
                sa[i0 * 64 + j]       = lo + Rj[jj];
                sa[(i0 + 1) * 64 + j] = hi + Rj[jj];
            }
    }
    __syncthreads();

    const int w = t >> 5, lane = t & 31;
#pragma unroll 1
    for (int rr = 0; rr < 8; rr++) {
        int i = w * 8 + rr;
        float v0 = sa[i * 64 + lane];
        float v1 = sa[i * 64 + 32 + lane];

        float m = fmaxf(v0, v1);
#pragma unroll
        for (int off = 16; off; off >>= 1)
            m = fmaxf(m, __shfl_xor_sync(0xffffffffu, m, off));
        float e0 = expf(v0 - m), e1 = expf(v1 - m);
        float ssum = e0 + e1;
#pragma unroll
        for (int off = 16; off; off >>= 1)
            ssum += __shfl_xor_sync(0xffffffffu, ssum, off);
        v0 = e0 / ssum;
        v1 = e1 / ssum;
        if (i < 32) { if (lane == i)      v0 = 0.f; }
        else        { if (lane == i - 32) v1 = 0.f; }

        sa[i * 64 + lane]      = v0;
        sa[i * 64 + 32 + lane] = v1;
        __syncwarp();

        uint32_t k0 = (__float_as_uint(v0) & 0xFFFFFFC0u) | (uint32_t)(63 - lane);
        uint32_t k1 = (__float_as_uint(v1) & 0xFFFFFFC0u) | (uint32_t)(31 - lane);

#pragma unroll
        for (int kk = 2; kk <= 32; kk <<= 1) {
#pragma unroll
            for (int j = kk >> 1; j >= 1; j >>= 1) {
                uint32_t o0 = __shfl_xor_sync(0xffffffffu, k0, j);
                uint32_t o1 = __shfl_xor_sync(0xffffffffu, k1, j);
                bool up = ((lane & j) == 0);
                bool d0c = ((lane & kk) == 0);
                bool d1c = (((lane + 32) & kk) == 0);
                k0 = (up == d0c) ? max(k0, o0) : min(k0, o0);
                k1 = (up == d1c) ? max(k1, o1) : min(k1, o1);
            }
        }
        {
            uint32_t mx = max(k0, k1), mn = min(k0, k1);
            k0 = mx; k1 = mn;
        }
#pragma unroll
        for (int j = 16; j >= 1; j >>= 1) {
            uint32_t o0 = __shfl_xor_sync(0xffffffffu, k0, j);
            uint32_t o1 = __shfl_xor_sync(0xffffffffu, k1, j);
            bool up = ((lane & j) == 0);
            k0 = up ? max(k0, o0) : min(k0, o0);
            k1 = up ? max(k1, o1) : min(k1, o1);
        }
        __syncwarp();

        if (lane < KTOP) {
            int j = 63 - (int)(k0 & 63u);
            float av = sa[i * 64 + j];
            int gi = b * NN + i;
            size_t e = (size_t)gi * KTOP + lane;
            out[e]                 = (float)gi;
            out[NEDGE_OUT + e]     = (float)(b * NN + j);
            out[2 * NEDGE_OUT + e] = av;
        }
        __syncwarp();
    }
}

// ---------------------------------------------------------------------------
extern "C" void kernel_launch(void* const* d_in, const int* in_sizes, int n_in,
                              void* d_out, int out_size)
{
    const float* x   = (const float*)d_in[0];
    const float* Wl  = (const float*)d_in[3];
    const float* bl  = (const float*)d_in[4];
    const float* Wr  = (const float*)d_in[5];
    const float* br  = (const float*)d_in[6];
    const float* att = (const float*)d_in[7];

    cudaMemcpyToSymbolAsync(c_att, att, 64 * sizeof(float), 0,
                            cudaMemcpyDeviceToDevice);
    splitwf_kernel<<<32, 256>>>(Wl, Wr);
    gemm_hmma<<<NTOT / 128, 256>>>(x, bl, br);
    attn_kernel<<<NB, 256>>>(att, (float*)d_out);
}

// round 7
// speedup vs baseline: 1.1658x; 1.1533x over previous
#include <cuda_runtime.h>
#include <cuda_bf16.h>
#include <cstdint>

#define NB     512
#define NN     64
#define INCH   256
#define KTOP   20
#define NTOT   (NB * NN)          // 32768 nodes
#define NEDGE_OUT (NTOT * KTOP)   // 655360

__device__ float g_y[(size_t)NTOT * 128];   // y[node][0:64]=x_l, [64:128]=x_r
__device__ uint2 g_wf[16 * 3 * 16 * 32];    // W frags [kc][s][nt][lane]
__constant__ float c_att[64];

// ---------------- packed f32x2 helpers ----------------
static __device__ __forceinline__ double pk2(float x, float y) {
    double r; asm("mov.b64 %0, {%1, %2};" : "=d"(r) : "f"(x), "f"(y)); return r;
}
static __device__ __forceinline__ void upk2(double v, float& x, float& y) {
    asm("mov.b64 {%0, %1}, %2;" : "=f"(x), "=f"(y) : "d"(v));
}
static __device__ __forceinline__ double fma2(double a, double b, double c) {
    double r; asm("fma.rn.f32x2 %0, %1, %2, %3;" : "=d"(r) : "d"(a), "d"(b), "d"(c)); return r;
}
static __device__ __forceinline__ double add2(double a, double b) {
    double r; asm("add.rn.f32x2 %0, %1, %2;" : "=d"(r) : "d"(a), "d"(b)); return r;
}
static __device__ __forceinline__ double and2(double a, double m) {
    double r; asm("and.b64 %0, %1, %2;" : "=d"(r) : "d"(a), "d"(m)); return r;
}

// ---------------- mma / ldmatrix helpers ----------------
static __device__ __forceinline__ uint32_t smem_u32(const void* p) {
    uint32_t a;
    asm("{ .reg .u64 t; cvta.to.shared.u64 t, %1; cvt.u32.u64 %0, t; }"
        : "=r"(a) : "l"(p));
    return a;
}
static __device__ __forceinline__ void ldmat4(uint32_t* r, uint32_t addr) {
    asm volatile("ldmatrix.sync.aligned.m8n8.x4.shared.b16 {%0,%1,%2,%3}, [%4];"
                 : "=r"(r[0]), "=r"(r[1]), "=r"(r[2]), "=r"(r[3]) : "r"(addr));
}
static __device__ __forceinline__ void mma16816(float* c, const uint32_t* a,
                                                uint32_t b0, uint32_t b1) {
    asm volatile(
        "mma.sync.aligned.m16n8k16.row.col.f32.bf16.bf16.f32 "
        "{%0,%1,%2,%3}, {%4,%5,%6,%7}, {%8,%9}, {%0,%1,%2,%3};"
        : "+f"(c[0]), "+f"(c[1]), "+f"(c[2]), "+f"(c[3])
        : "r"(a[0]), "r"(a[1]), "r"(a[2]), "r"(a[3]), "r"(b0), "r"(b1));
}

static __device__ __forceinline__ void split3(
    float a, unsigned short& s0, unsigned short& s1, unsigned short& s2)
{
    __nv_bfloat16 h0 = __float2bfloat16(a);
    float r1 = a - __bfloat162float(h0);
    __nv_bfloat16 h1 = __float2bfloat16(r1);
    float r2 = r1 - __bfloat162float(h1);
    __nv_bfloat16 h2 = __float2bfloat16(r2);
    s0 = __bfloat16_as_ushort(h0);
    s1 = __bfloat16_as_ushort(h1);
    s2 = __bfloat16_as_ushort(h2);
}

// ---------------------------------------------------------------------------
// Kernel 0: W -> bf16x3 B-fragments (lean version, measured neutral)
// ---------------------------------------------------------------------------
__global__ __launch_bounds__(256) void splitwf_kernel(
    const float* __restrict__ Wl, const float* __restrict__ Wr)
{
    int g = blockIdx.x * 256 + threadIdx.x;     // < 8192
    int lane = g & 31, nt = (g >> 5) & 15, kc = g >> 9;
    int n = nt * 8 + (lane >> 2);
    int k = kc * 16 + 2 * (lane & 3);
    const float* wrow = (n < 64) ? (Wl + (size_t)n * INCH)
                                 : (Wr + (size_t)(n - 64) * INCH);
    float2 wlo = *(const float2*)(wrow + k);
    float2 whi = *(const float2*)(wrow + k + 8);
    unsigned short a0[4], a1[4], a2[4];
    split3(wlo.x, a0[0], a1[0], a2[0]);
    split3(wlo.y, a0[1], a1[1], a2[1]);
    split3(whi.x, a0[2], a1[2], a2[2]);
    split3(whi.y, a0[3], a1[3], a2[3]);
    size_t base = ((size_t)(kc * 3) * 16 + nt) * 32 + lane;
    g_wf[base]        = make_uint2((uint32_t)a0[0] | ((uint32_t)a0[1] << 16),
                                   (uint32_t)a0[2] | ((uint32_t)a0[3] << 16));
    g_wf[base + 512]  = make_uint2((uint32_t)a1[0] | ((uint32_t)a1[1] << 16),
                                   (uint32_t)a1[2] | ((uint32_t)a1[3] << 16));
    g_wf[base + 1024] = make_uint2((uint32_t)a2[0] | ((uint32_t)a2[1] << 16),
                                   (uint32_t)a2[2] | ((uint32_t)a2[3] << 16));
}

// ---------------------------------------------------------------------------
// Kernel 1: HMMA dual GEMM — R4 single-buffer structure + register prefetch
// of the next x chunk (2x LDG.128 issued under the MMA loop).
// ---------------------------------------------------------------------------
__global__ __launch_bounds__(256) void gemm_hmma(
    const float* __restrict__ x,
    const float* __restrict__ bl, const float* __restrict__ br)
{
    __shared__ __align__(16) unsigned short sA[3][128 * 24];  // 18.4KB
    __shared__ float sbias[128];

    const int t = threadIdx.x, wid = t >> 5, lane = t & 31;
    const int m0 = blockIdx.x * 128;
    if (t < 128) sbias[t] = (t < 64) ? bl[t] : br[t - 64];

    float acc[16][4];
#pragma unroll
    for (int nt = 0; nt < 16; nt++)
#pragma unroll
        for (int v = 0; v < 4; v++) acc[nt][v] = 0.f;

    // per-thread staging coordinates (2 float4 per chunk)
    const int row0 = t >> 2,        q0 = t & 3;          // v = t
    const int row1 = (t + 256) >> 2, q1 = (t + 256) & 3; // v = t+256
    const float* xp0 = x + (size_t)(m0 + row0) * INCH + q0 * 4;
    const float* xp1 = x + (size_t)(m0 + row1) * INCH + q1 * 4;

    const uint32_t aoff = (uint32_t)((wid * 16 + ((lane >> 3) & 1) * 8 + (lane & 7)) * 24
                                     + (lane >> 4) * 8) * 2;
    const uint32_t sa0 = smem_u32(&sA[0][0]);

    // prefetch chunk 0
    float4 pf0 = *(const float4*)(xp0);
    float4 pf1 = *(const float4*)(xp1);

    for (int kc = 0; kc < 16; kc++) {
        // split + store staged registers (A-fragments dead here)
        {
            unsigned short a0[4], a1[4], a2[4];
            split3(pf0.x, a0[0], a1[0], a2[0]);
            split3(pf0.y, a0[1], a1[1], a2[1]);
            split3(pf0.z, a0[2], a1[2], a2[2]);
            split3(pf0.w, a0[3], a1[3], a2[3]);
            int off = row0 * 24 + q0 * 4;
            *(uint2*)&sA[0][off] = make_uint2((uint32_t)a0[0] | ((uint32_t)a0[1] << 16),
                                              (uint32_t)a0[2] | ((uint32_t)a0[3] << 16));
            *(uint2*)&sA[1][off] = make_uint2((uint32_t)a1[0] | ((uint32_t)a1[1] << 16),
                                              (uint32_t)a1[2] | ((uint32_t)a1[3] << 16));
            *(uint2*)&sA[2][off] = make_uint2((uint32_t)a2[0] | ((uint32_t)a2[1] << 16),
                                              (uint32_t)a2[2] | ((uint32_t)a2[3] << 16));
            split3(pf1.x, a0[0], a1[0], a2[0]);
            split3(pf1.y, a0[1], a1[1], a2[1]);
            split3(pf1.z, a0[2], a1[2], a2[2]);
            split3(pf1.w, a0[3], a1[3], a2[3]);
            off = row1 * 24 + q1 * 4;
            *(uint2*)&sA[0][off] = make_uint2((uint32_t)a0[0] | ((uint32_t)a0[1] << 16),
                                              (uint32_t)a0[2] | ((uint32_t)a0[3] << 16));
            *(uint2*)&sA[1][off] = make_uint2((uint32_t)a1[0] | ((uint32_t)a1[1] << 16),
                                              (uint32_t)a1[2] | ((uint32_t)a1[3] << 16));
            *(uint2*)&sA[2][off] = make_uint2((uint32_t)a2[0] | ((uint32_t)a2[1] << 16),
                                              (uint32_t)a2[2] | ((uint32_t)a2[3] << 16));
        }
        __syncthreads();

        uint32_t A0[4], A1[4], A2[4];
        ldmat4(A0, sa0 + aoff);
        ldmat4(A1, sa0 + 128 * 24 * 2 + aoff);
        ldmat4(A2, sa0 + 2 * 128 * 24 * 2 + aoff);

        // issue next chunk's global loads; latency hides under the MMA loop
        if (kc < 15) {
            pf0 = *(const float4*)(xp0 + (kc + 1) * 16);
            pf1 = *(const float4*)(xp1 + (kc + 1) * 16);
        }

        const uint2* wf = g_wf + (size_t)(kc * 3) * 512 + lane;
#pragma unroll
        for (int nt = 0; nt < 16; nt++) {
            uint2 B0 = __ldg(wf + nt * 32);
            uint2 B1 = __ldg(wf + 512 + nt * 32);
            uint2 B2 = __ldg(wf + 1024 + nt * 32);
            mma16816(acc[nt], A0, B0.x, B0.y);
            mma16816(acc[nt], A0, B1.x, B1.y);
            mma16816(acc[nt], A1, B0.x, B0.y);
            mma16816(acc[nt], A1, B1.x, B1.y);
            mma16816(acc[nt], A0, B2.x, B2.y);
            mma16816(acc[nt], A2, B0.x, B0.y);
        }
        __syncthreads();
    }

    const int r0 = m0 + wid * 16 + (lane >> 2);
    const int cbase = 2 * (lane & 3);
#pragma unroll
    for (int nt = 0; nt < 16; nt++) {
        int c = nt * 8 + cbase;
        float2 o0 = make_float2(acc[nt][0] + sbias[c], acc[nt][1] + sbias[c + 1]);
        float2 o1 = make_float2(acc[nt][2] + sbias[c], acc[nt][3] + sbias[c + 1]);
        *(float2*)&g_y[(size_t)r0 * 128 + c] = o0;
        *(float2*)&g_y[(size_t)(r0 + 8) * 128 + c] = o1;
    }
}

// ---------------------------------------------------------------------------
// Kernel 2: attention — EXACT R4 version
// ---------------------------------------------------------------------------
__global__ __launch_bounds__(256) void attn_kernel(
    const float* __restrict__ att, float* __restrict__ out)
{
    __shared__ float sxl[4096];
    __shared__ float sxr[4096];
    __shared__ float sa [4096];

    const int t = threadIdx.x;
    const int b = blockIdx.x;
    const float* yg = g_y + (size_t)b * NN * 128;

#pragma unroll
    for (int s = 0; s < 8; s++) {
        int v = t + s * 256;
        int node = v >> 5, q = v & 31;
        float4 p = *(const float4*)(yg + (size_t)node * 128 + q * 4);
        if (q < 16) {
            int pi = node >> 1, comp = node & 1, swz = pi & 3;
            int d0 = q * 4;
            int base = pi * 128 + comp;
            sxl[base + ((d0 + 0) ^ swz) * 2] = p.x;
            sxl[base + ((d0 + 1) ^ swz) * 2] = p.y;
            sxl[base + ((d0 + 2) ^ swz) * 2] = p.z;
            sxl[base + ((d0 + 3) ^ swz) * 2] = p.w;
        } else {
            int d0 = (q - 16) * 4, sw = (node >> 2) & 15;
            int base = node * 64;
            sxr[base + ((d0 + 0) ^ sw)] = p.x;
            sxr[base + ((d0 + 1) ^ sw)] = p.y;
            sxr[base + ((d0 + 2) ^ sw)] = p.z;
            sxr[base + ((d0 + 3) ^ sw)] = p.w;
        }
    }
    __syncthreads();

    {
        int w = t >> 5, lane = t & 31;
        float a0 = 0.6f * att[lane];
        float a1 = 0.6f * att[lane + 32];
#pragma unroll
        for (int jj = 0; jj < 8; jj++) {
            int j = w * 8 + jj, sw = (j >> 2) & 15;
            float r = fmaf(a0, sxr[j * 64 + (lane ^ sw)],
                           a1 * sxr[j * 64 + ((lane + 32) ^ sw)]);
#pragma unroll
            for (int off = 16; off; off >>= 1)
                r += __shfl_xor_sync(0xffffffffu, r, off);
            if (lane == 0) sa[j] = r;
        }
    }
    __syncthreads();

    const int tR = t >> 4, tC = t & 15;
    float Rj[4];
#pragma unroll
    for (int jj = 0; jj < 4; jj++) Rj[jj] = sa[tC * 4 + jj];

    {
        const double ABSM = __longlong_as_double(0x7fffffff7fffffffLL);
        const double* sxl2 = (const double*)sxl;
        const double* pA = sxl2 + (2 * tR) * 64;
        const double* pB = sxl2 + (2 * tR + 1) * 64;
        const float*  pR = sxr + (4 * tC) * 64;
        const int swz0 = (2 * tR) & 3;
        double acc[2][4];
#pragma unroll
        for (int pr = 0; pr < 2; pr++)
#pragma unroll
            for (int jj = 0; jj < 4; jj++) acc[pr][jj] = 0.0;

#pragma unroll 8
        for (int d = 0; d < 64; d++) {
            int dd = d ^ swz0;
            double xa = pA[dd];
            double xb = pB[dd ^ 1];
            int ddr = d ^ tC;
            double r0 = pk2(pR[ddr],        pR[ddr]);
            double r1 = pk2(pR[64 + ddr],   pR[64 + ddr]);
            double r2 = pk2(pR[128 + ddr],  pR[128 + ddr]);
            double r3 = pk2(pR[192 + ddr],  pR[192 + ddr]);
            float a4 = 0.4f * c_att[d];
            double a42 = pk2(a4, a4);
            acc[0][0] = fma2(a42, and2(add2(xa, r0), ABSM), acc[0][0]);
            acc[0][1] = fma2(a42, and2(add2(xa, r1), ABSM), acc[0][1]);
            acc[0][2] = fma2(a42, and2(add2(xa, r2), ABSM), acc[0][2]);
            acc[0][3] = fma2(a42, and2(add2(xa, r3), ABSM), acc[0][3]);
            acc[1][0] = fma2(a42, and2(add2(xb, r0), ABSM), acc[1][0]);
            acc[1][1] = fma2(a42, and2(add2(xb, r1), ABSM), acc[1][1]);
            acc[1][2] = fma2(a42, and2(add2(xb, r2), ABSM), acc[1][2]);
            acc[1][3] = fma2(a42, and2(add2(xb, r3), ABSM), acc[1][3]);
        }

        __syncthreads();
#pragma unroll
        for (int pr = 0; pr < 2; pr++)
#pragma unroll
            for (int jj = 0; jj < 4; jj++) {
                float lo, hi; upk2(acc[pr][jj], lo, hi);
                int i0 = tR * 4 + pr * 2, j = tC * 4 + jj;
                sa[i0 * 64 + j]       = lo + Rj[jj];
                sa[(i0 + 1) * 64 + j] = hi + Rj[jj];
            }
    }
    __syncthreads();

    const int w = t >> 5, lane = t & 31;
#pragma unroll 1
    for (int rr = 0; rr < 8; rr++) {
        int i = w * 8 + rr;
        float v0 = sa[i * 64 + lane];
        float v1 = sa[i * 64 + 32 + lane];

        float m = fmaxf(v0, v1);
#pragma unroll
        for (int off = 16; off; off >>= 1)
            m = fmaxf(m, __shfl_xor_sync(0xffffffffu, m, off));
        float e0 = expf(v0 - m), e1 = expf(v1 - m);
        float ssum = e0 + e1;
#pragma unroll
        for (int off = 16; off; off >>= 1)
            ssum += __shfl_xor_sync(0xffffffffu, ssum, off);
        v0 = e0 / ssum;
        v1 = e1 / ssum;
        if (i < 32) { if (lane == i)      v0 = 0.f; }
        else        { if (lane == i - 32) v1 = 0.f; }

        sa[i * 64 + lane]      = v0;
        sa[i * 64 + 32 + lane] = v1;
        __syncwarp();

        uint32_t k0 = (__float_as_uint(v0) & 0xFFFFFFC0u) | (uint32_t)(63 - lane);
        uint32_t k1 = (__float_as_uint(v1) & 0xFFFFFFC0u) | (uint32_t)(31 - lane);

#pragma unroll
        for (int kk = 2; kk <= 32; kk <<= 1) {
#pragma unroll
            for (int j = kk >> 1; j >= 1; j >>= 1) {
                uint32_t o0 = __shfl_xor_sync(0xffffffffu, k0, j);
                uint32_t o1 = __shfl_xor_sync(0xffffffffu, k1, j);
                bool up = ((lane & j) == 0);
                bool d0c = ((lane & kk) == 0);
                bool d1c = (((lane + 32) & kk) == 0);
                k0 = (up == d0c) ? max(k0, o0) : min(k0, o0);
                k1 = (up == d1c) ? max(k1, o1) : min(k1, o1);
            }
        }
        {
            uint32_t mx = max(k0, k1), mn = min(k0, k1);
            k0 = mx; k1 = mn;
        }
#pragma unroll
        for (int j = 16; j >= 1; j >>= 1) {
            uint32_t o0 = __shfl_xor_sync(0xffffffffu, k0, j);
            uint32_t o1 = __shfl_xor_sync(0xffffffffu, k1, j);
            bool up = ((lane & j) == 0);
            k0 = up ? max(k0, o0) : min(k0, o0);
            k1 = up ? max(k1, o1) : min(k1, o1);
        }
        __syncwarp();

        if (lane < KTOP) {
            int j = 63 - (int)(k0 & 63u);
            float av = sa[i * 64 + j];
            int gi = b * NN + i;
            size_t e = (size_t)gi * KTOP + lane;
            out[e]                 = (float)gi;
            out[NEDGE_OUT + e]     = (float)(b * NN + j);
            out[2 * NEDGE_OUT + e] = av;
        }
        __syncwarp();
    }
}

// ---------------------------------------------------------------------------
extern "C" void kernel_launch(void* const* d_in, const int* in_sizes, int n_in,
                              void* d_out, int out_size)
{
    const float* x   = (const float*)d_in[0];
    const float* Wl  = (const float*)d_in[3];
    const float* bl  = (const float*)d_in[4];
    const float* Wr  = (const float*)d_in[5];
    const float* br  = (const float*)d_in[6];
    const float* att = (const float*)d_in[7];

    cudaMemcpyToSymbolAsync(c_att, att, 64 * sizeof(float), 0,
                            cudaMemcpyDeviceToDevice);
    splitwf_kernel<<<32, 256>>>(Wl, Wr);
    gemm_hmma<<<NTOT / 128, 256>>>(x, bl, br);
    attn_kernel<<<NB, 256>>>(att, (float*)d_out);
}

// round 8
// speedup vs baseline: 1.6081x; 1.3794x over previous
#include <cuda_runtime.h>
#include <cuda_bf16.h>
#include <cstdint>

#define NB     512
#define NN     64
#define INCH   256
#define KTOP   20
#define NTOT   (NB * NN)          // 32768 nodes
#define NEDGE_OUT (NTOT * KTOP)   // 655360

__device__ float g_y[(size_t)NTOT * 128];   // y[node][0:64]=x_l, [64:128]=x_r
__device__ uint2 g_wf[16 * 3 * 16 * 32];    // W frags [kc][s][nt][lane]
__constant__ float c_att[64];

// ---------------- packed f32x2 helpers ----------------
static __device__ __forceinline__ double pk2(float x, float y) {
    double r; asm("mov.b64 %0, {%1, %2};" : "=d"(r) : "f"(x), "f"(y)); return r;
}
static __device__ __forceinline__ void upk2(double v, float& x, float& y) {
    asm("mov.b64 {%0, %1}, %2;" : "=f"(x), "=f"(y) : "d"(v));
}
static __device__ __forceinline__ double fma2(double a, double b, double c) {
    double r; asm("fma.rn.f32x2 %0, %1, %2, %3;" : "=d"(r) : "d"(a), "d"(b), "d"(c)); return r;
}
static __device__ __forceinline__ double add2(double a, double b) {
    double r; asm("add.rn.f32x2 %0, %1, %2;" : "=d"(r) : "d"(a), "d"(b)); return r;
}
static __device__ __forceinline__ double and2(double a, double m) {
    double r; asm("and.b64 %0, %1, %2;" : "=d"(r) : "d"(a), "d"(m)); return r;
}

// ---------------- mma / ldmatrix helpers ----------------
static __device__ __forceinline__ uint32_t smem_u32(const void* p) {
    uint32_t a;
    asm("{ .reg .u64 t; cvta.to.shared.u64 t, %1; cvt.u32.u64 %0, t; }"
        : "=r"(a) : "l"(p));
    return a;
}
static __device__ __forceinline__ void ldmat4(uint32_t* r, uint32_t addr) {
    asm volatile("ldmatrix.sync.aligned.m8n8.x4.shared.b16 {%0,%1,%2,%3}, [%4];"
                 : "=r"(r[0]), "=r"(r[1]), "=r"(r[2]), "=r"(r[3]) : "r"(addr));
}
static __device__ __forceinline__ void mma16816(float* c, const uint32_t* a,
                                                uint32_t b0, uint32_t b1) {
    asm volatile(
        "mma.sync.aligned.m16n8k16.row.col.f32.bf16.bf16.f32 "
        "{%0,%1,%2,%3}, {%4,%5,%6,%7}, {%8,%9}, {%0,%1,%2,%3};"
        : "+f"(c[0]), "+f"(c[1]), "+f"(c[2]), "+f"(c[3])
        : "r"(a[0]), "r"(a[1]), "r"(a[2]), "r"(a[3]), "r"(b0), "r"(b1));
}

static __device__ __forceinline__ void split3(
    float a, unsigned short& s0, unsigned short& s1, unsigned short& s2)
{
    __nv_bfloat16 h0 = __float2bfloat16(a);
    float r1 = a - __bfloat162float(h0);
    __nv_bfloat16 h1 = __float2bfloat16(r1);
    float r2 = r1 - __bfloat162float(h1);
    __nv_bfloat16 h2 = __float2bfloat16(r2);
    s0 = __bfloat16_as_ushort(h0);
    s1 = __bfloat16_as_ushort(h1);
    s2 = __bfloat16_as_ushort(h2);
}

// ---------------------------------------------------------------------------
// Kernel 0: W -> bf16x3 B-fragments (lean version, measured neutral)
// ---------------------------------------------------------------------------
__global__ __launch_bounds__(256) void splitwf_kernel(
    const float* __restrict__ Wl, const float* __restrict__ Wr)
{
    int g = blockIdx.x * 256 + threadIdx.x;     // < 8192
    int lane = g & 31, nt = (g >> 5) & 15, kc = g >> 9;
    int n = nt * 8 + (lane >> 2);
    int k = kc * 16 + 2 * (lane & 3);
    const float* wrow = (n < 64) ? (Wl + (size_t)n * INCH)
                                 : (Wr + (size_t)(n - 64) * INCH);
    float2 wlo = *(const float2*)(wrow + k);
    float2 whi = *(const float2*)(wrow + k + 8);
    unsigned short a0[4], a1[4], a2[4];
    split3(wlo.x, a0[0], a1[0], a2[0]);
    split3(wlo.y, a0[1], a1[1], a2[1]);
    split3(whi.x, a0[2], a1[2], a2[2]);
    split3(whi.y, a0[3], a1[3], a2[3]);
    size_t base = ((size_t)(kc * 3) * 16 + nt) * 32 + lane;
    g_wf[base]        = make_uint2((uint32_t)a0[0] | ((uint32_t)a0[1] << 16),
                                   (uint32_t)a0[2] | ((uint32_t)a0[3] << 16));
    g_wf[base + 512]  = make_uint2((uint32_t)a1[0] | ((uint32_t)a1[1] << 16),
                                   (uint32_t)a1[2] | ((uint32_t)a1[3] << 16));
    g_wf[base + 1024] = make_uint2((uint32_t)a2[0] | ((uint32_t)a2[1] << 16),
                                   (uint32_t)a2[2] | ((uint32_t)a2[3] << 16));
}

// ---------------------------------------------------------------------------
// Kernel 1: HMMA dual GEMM — EXACT R4 structure (known-good; no live state
// across the MMA loop, staging temps only in the dead inter-barrier window).
// ---------------------------------------------------------------------------
__global__ __launch_bounds__(256) void gemm_hmma(
    const float* __restrict__ x,
    const float* __restrict__ bl, const float* __restrict__ br)
{
    __shared__ __align__(16) unsigned short sA[3][128 * 24];  // 48B row stride
    __shared__ float sbias[128];

    const int t = threadIdx.x, wid = t >> 5, lane = t & 31;
    const int m0 = blockIdx.x * 128;
    if (t < 128) sbias[t] = (t < 64) ? bl[t] : br[t - 64];

    float acc[16][4];
#pragma unroll
    for (int nt = 0; nt < 16; nt++)
#pragma unroll
        for (int v = 0; v < 4; v++) acc[nt][v] = 0.f;

    uint32_t abase[3];
    {
        int row_off = wid * 16 + ((lane >> 3) & 1) * 8 + (lane & 7);
        int col8 = (lane >> 4) * 8;
#pragma unroll
        for (int s = 0; s < 3; s++)
            abase[s] = smem_u32(&sA[s][0]) + (uint32_t)(row_off * 24 + col8) * 2;
    }

    for (int kc = 0; kc < 16; kc++) {
#pragma unroll
        for (int ss = 0; ss < 2; ss++) {
            int v = t + ss * 256;          // 0..511 float4 ids
            int row = v >> 2, q = v & 3;
            float4 p = *(const float4*)(x + (size_t)(m0 + row) * INCH + kc * 16 + q * 4);
            unsigned short a0[4], a1[4], a2[4];
            split3(p.x, a0[0], a1[0], a2[0]);
            split3(p.y, a0[1], a1[1], a2[1]);
            split3(p.z, a0[2], a1[2], a2[2]);
            split3(p.w, a0[3], a1[3], a2[3]);
            int off = row * 24 + q * 4;
            *(uint2*)&sA[0][off] = make_uint2((uint32_t)a0[0] | ((uint32_t)a0[1] << 16),
                                              (uint32_t)a0[2] | ((uint32_t)a0[3] << 16));
            *(uint2*)&sA[1][off] = make_uint2((uint32_t)a1[0] | ((uint32_t)a1[1] << 16),
                                              (uint32_t)a1[2] | ((uint32_t)a1[3] << 16));
            *(uint2*)&sA[2][off] = make_uint2((uint32_t)a2[0] | ((uint32_t)a2[1] << 16),
                                              (uint32_t)a2[2] | ((uint32_t)a2[3] << 16));
        }
        __syncthreads();

        uint32_t A0[4], A1[4], A2[4];
        ldmat4(A0, abase[0]);
        ldmat4(A1, abase[1]);
        ldmat4(A2, abase[2]);

        const uint2* wf = g_wf + (size_t)(kc * 3) * 512 + lane;
#pragma unroll
        for (int nt = 0; nt < 16; nt++) {
            uint2 B0 = __ldg(wf + nt * 32);
            uint2 B1 = __ldg(wf + 512 + nt * 32);
            uint2 B2 = __ldg(wf + 1024 + nt * 32);
            mma16816(acc[nt], A0, B0.x, B0.y);
            mma16816(acc[nt], A0, B1.x, B1.y);
            mma16816(acc[nt], A1, B0.x, B0.y);
            mma16816(acc[nt], A1, B1.x, B1.y);
            mma16816(acc[nt], A0, B2.x, B2.y);
            mma16816(acc[nt], A2, B0.x, B0.y);
        }
        __syncthreads();
    }

    const int r0 = m0 + wid * 16 + (lane >> 2);
    const int cbase = 2 * (lane & 3);
#pragma unroll
    for (int nt = 0; nt < 16; nt++) {
        int c = nt * 8 + cbase;
        float2 o0 = make_float2(acc[nt][0] + sbias[c], acc[nt][1] + sbias[c + 1]);
        float2 o1 = make_float2(acc[nt][2] + sbias[c], acc[nt][3] + sbias[c + 1]);
        *(float2*)&g_y[(size_t)r0 * 128 + c] = o0;
        *(float2*)&g_y[(size_t)(r0 + 8) * 128 + c] = o1;
    }
}

// ---------------------------------------------------------------------------
// Kernel 2: attention. Phases 1/1.5/2 exact R4. Phase 3: two rows processed
// concurrently per iteration (independent shfl chains -> 2x ILP on the
// latency-bound softmax reductions + bitonic sort). Per-row math identical.
// ---------------------------------------------------------------------------
__global__ __launch_bounds__(256) void attn_kernel(
    const float* __restrict__ att, float* __restrict__ out)
{
    __shared__ float sxl[4096];
    __shared__ float sxr[4096];
    __shared__ float sa [4096];

    const int t = threadIdx.x;
    const int b = blockIdx.x;
    const float* yg = g_y + (size_t)b * NN * 128;

#pragma unroll
    for (int s = 0; s < 8; s++) {
        int v = t + s * 256;
        int node = v >> 5, q = v & 31;
        float4 p = *(const float4*)(yg + (size_t)node * 128 + q * 4);
        if (q < 16) {
            int pi = node >> 1, comp = node & 1, swz = pi & 3;
            int d0 = q * 4;
            int base = pi * 128 + comp;
            sxl[base + ((d0 + 0) ^ swz) * 2] = p.x;
            sxl[base + ((d0 + 1) ^ swz) * 2] = p.y;
            sxl[base + ((d0 + 2) ^ swz) * 2] = p.z;
            sxl[base + ((d0 + 3) ^ swz) * 2] = p.w;
        } else {
            int d0 = (q - 16) * 4, sw = (node >> 2) & 15;
            int base = node * 64;
            sxr[base + ((d0 + 0) ^ sw)] = p.x;
            sxr[base + ((d0 + 1) ^ sw)] = p.y;
            sxr[base + ((d0 + 2) ^ sw)] = p.z;
            sxr[base + ((d0 + 3) ^ sw)] = p.w;
        }
    }
    __syncthreads();

    {
        int w = t >> 5, lane = t & 31;
        float a0 = 0.6f * att[lane];
        float a1 = 0.6f * att[lane + 32];
#pragma unroll
        for (int jj = 0; jj < 8; jj++) {
            int j = w * 8 + jj, sw = (j >> 2) & 15;
            float r = fmaf(a0, sxr[j * 64 + (lane ^ sw)],
                           a1 * sxr[j * 64 + ((lane + 32) ^ sw)]);
#pragma unroll
            for (int off = 16; off; off >>= 1)
                r += __shfl_xor_sync(0xffffffffu, r, off);
            if (lane == 0) sa[j] = r;
        }
    }
    __syncthreads();

    const int tR = t >> 4, tC = t & 15;
    float Rj[4];
#pragma unroll
    for (int jj = 0; jj < 4; jj++) Rj[jj] = sa[tC * 4 + jj];

    {
        const double ABSM = __longlong_as_double(0x7fffffff7fffffffLL);
        const double* sxl2 = (const double*)sxl;
        const double* pA = sxl2 + (2 * tR) * 64;
        const double* pB = sxl2 + (2 * tR + 1) * 64;
        const float*  pR = sxr + (4 * tC) * 64;
        const int swz0 = (2 * tR) & 3;
        double acc[2][4];
#pragma unroll
        for (int pr = 0; pr < 2; pr++)
#pragma unroll
            for (int jj = 0; jj < 4; jj++) acc[pr][jj] = 0.0;

#pragma unroll 8
        for (int d = 0; d < 64; d++) {
            int dd = d ^ swz0;
            double xa = pA[dd];
            double xb = pB[dd ^ 1];
            int ddr = d ^ tC;
            double r0 = pk2(pR[ddr],        pR[ddr]);
            double r1 = pk2(pR[64 + ddr],   pR[64 + ddr]);
            double r2 = pk2(pR[128 + ddr],  pR[128 + ddr]);
            double r3 = pk2(pR[192 + ddr],  pR[192 + ddr]);
            float a4 = 0.4f * c_att[d];
            double a42 = pk2(a4, a4);
            acc[0][0] = fma2(a42, and2(add2(xa, r0), ABSM), acc[0][0]);
            acc[0][1] = fma2(a42, and2(add2(xa, r1), ABSM), acc[0][1]);
            acc[0][2] = fma2(a42, and2(add2(xa, r2), ABSM), acc[0][2]);
            acc[0][3] = fma2(a42, and2(add2(xa, r3), ABSM), acc[0][3]);
            acc[1][0] = fma2(a42, and2(add2(xb, r0), ABSM), acc[1][0]);
            acc[1][1] = fma2(a42, and2(add2(xb, r1), ABSM), acc[1][1]);
            acc[1][2] = fma2(a42, and2(add2(xb, r2), ABSM), acc[1][2]);
            acc[1][3] = fma2(a42, and2(add2(xb, r3), ABSM), acc[1][3]);
        }

        __syncthreads();
#pragma unroll
        for (int pr = 0; pr < 2; pr++)
#pragma unroll
            for (int jj = 0; jj < 4; jj++) {
                float lo, hi; upk2(acc[pr][jj], lo, hi);
                int i0 = tR * 4 + pr * 2, j = tC * 4 + jj;
                sa[i0 * 64 + j]       = lo + Rj[jj];
                sa[(i0 + 1) * 64 + j] = hi + Rj[jj];
            }
    }
    __syncthreads();

    // ---- Phase 3: softmax + bitonic top-20, TWO rows in flight ----
    const int w = t >> 5, lane = t & 31;
#pragma unroll 1
    for (int rp = 0; rp < 4; rp++) {
        int iA = w * 8 + rp * 2;
        int iB = iA + 1;
        float v0a = sa[iA * 64 + lane], v1a = sa[iA * 64 + 32 + lane];
        float v0b = sa[iB * 64 + lane], v1b = sa[iB * 64 + 32 + lane];

        float ma = fmaxf(v0a, v1a), mb = fmaxf(v0b, v1b);
#pragma unroll
        for (int off = 16; off; off >>= 1) {
            ma = fmaxf(ma, __shfl_xor_sync(0xffffffffu, ma, off));
            mb = fmaxf(mb, __shfl_xor_sync(0xffffffffu, mb, off));
        }
        float e0a = expf(v0a - ma), e1a = expf(v1a - ma);
        float e0b = expf(v0b - mb), e1b = expf(v1b - mb);
        float sma = e0a + e1a, smb = e0b + e1b;
#pragma unroll
        for (int off = 16; off; off >>= 1) {
            sma += __shfl_xor_sync(0xffffffffu, sma, off);
            smb += __shfl_xor_sync(0xffffffffu, smb, off);
        }
        v0a = e0a / sma; v1a = e1a / sma;
        v0b = e0b / smb; v1b = e1b / smb;
        if (iA < 32) { if (lane == iA)      v0a = 0.f; }
        else         { if (lane == iA - 32) v1a = 0.f; }
        if (iB < 32) { if (lane == iB)      v0b = 0.f; }
        else         { if (lane == iB - 32) v1b = 0.f; }

        sa[iA * 64 + lane]      = v0a;
        sa[iA * 64 + 32 + lane] = v1a;
        sa[iB * 64 + lane]      = v0b;
        sa[iB * 64 + 32 + lane] = v1b;
        __syncwarp();

        uint32_t k0a = (__float_as_uint(v0a) & 0xFFFFFFC0u) | (uint32_t)(63 - lane);
        uint32_t k1a = (__float_as_uint(v1a) & 0xFFFFFFC0u) | (uint32_t)(31 - lane);
        uint32_t k0b = (__float_as_uint(v0b) & 0xFFFFFFC0u) | (uint32_t)(63 - lane);
        uint32_t k1b = (__float_as_uint(v1b) & 0xFFFFFFC0u) | (uint32_t)(31 - lane);

#pragma unroll
        for (int kk = 2; kk <= 32; kk <<= 1) {
#pragma unroll
            for (int j = kk >> 1; j >= 1; j >>= 1) {
                uint32_t o0a = __shfl_xor_sync(0xffffffffu, k0a, j);
                uint32_t o1a = __shfl_xor_sync(0xffffffffu, k1a, j);
                uint32_t o0b = __shfl_xor_sync(0xffffffffu, k0b, j);
                uint32_t o1b = __shfl_xor_sync(0xffffffffu, k1b, j);
                bool up = ((lane & j) == 0);
                bool d0c = ((lane & kk) == 0);
                bool d1c = (((lane + 32) & kk) == 0);
                k0a = (up == d0c) ? max(k0a, o0a) : min(k0a, o0a);
                k1a = (up == d1c) ? max(k1a, o1a) : min(k1a, o1a);
                k0b = (up == d0c) ? max(k0b, o0b) : min(k0b, o0b);
                k1b = (up == d1c) ? max(k1b, o1b) : min(k1b, o1b);
            }
        }
        {
            uint32_t mxa = max(k0a, k1a), mna = min(k0a, k1a);
            k0a = mxa; k1a = mna;
            uint32_t mxb = max(k0b, k1b), mnb = min(k0b, k1b);
            k0b = mxb; k1b = mnb;
        }
#pragma unroll
        for (int j = 16; j >= 1; j >>= 1) {
            uint32_t o0a = __shfl_xor_sync(0xffffffffu, k0a, j);
            uint32_t o1a = __shfl_xor_sync(0xffffffffu, k1a, j);
            uint32_t o0b = __shfl_xor_sync(0xffffffffu, k0b, j);
            uint32_t o1b = __shfl_xor_sync(0xffffffffu, k1b, j);
            bool up = ((lane & j) == 0);
            k0a = up ? max(k0a, o0a) : min(k0a, o0a);
            k1a = up ? max(k1a, o1a) : min(k1a, o1a);
            k0b = up ? max(k0b, o0b) : min(k0b, o0b);
            k1b = up ? max(k1b, o1b) : min(k1b, o1b);
        }
        __syncwarp();

        if (lane < KTOP) {
            int ja = 63 - (int)(k0a & 63u);
            int jb = 63 - (int)(k0b & 63u);
            float ava = sa[iA * 64 + ja];
            float avb = sa[iB * 64 + jb];
            int giA = b * NN + iA;
            int giB = b * NN + iB;
            size_t eA = (size_t)giA * KTOP + lane;
            size_t eB = (size_t)giB * KTOP + lane;
            out[eA]                 = (float)giA;
            out[NEDGE_OUT + eA]     = (float)(b * NN + ja);
            out[2 * NEDGE_OUT + eA] = ava;
            out[eB]                 = (float)giB;
            out[NEDGE_OUT + eB]     = (float)(b * NN + jb);
            out[2 * NEDGE_OUT + eB] = avb;
        }
        __syncwarp();
    }
}

// ---------------------------------------------------------------------------
extern "C" void kernel_launch(void* const* d_in, const int* in_sizes, int n_in,
                              void* d_out, int out_size)
{
    const float* x   = (const float*)d_in[0];
    const float* Wl  = (const float*)d_in[3];
    const float* bl  = (const float*)d_in[4];
    const float* Wr  = (const float*)d_in[5];
    const float* br  = (const float*)d_in[6];
    const float* att = (const float*)d_in[7];

    cudaMemcpyToSymbolAsync(c_att, att, 64 * sizeof(float), 0,
                            cudaMemcpyDeviceToDevice);
    splitwf_kernel<<<32, 256>>>(Wl, Wr);
    gemm_hmma<<<NTOT / 128, 256>>>(x, bl, br);
    attn_kernel<<<NB, 256>>>(att, (float*)d_out);
}